// round 1
// baseline (speedup 1.0000x reference)
#include <cuda_runtime.h>

#define B_ 4
#define D_ 1024
#define N_ 2048
#define H_ 16
#define HD_ 64
#define DN_ ((size_t)D_ * N_)

// Scratch: device globals (no runtime allocation allowed)
__device__ float g_Q[B_ * D_ * N_];
__device__ float g_K[B_ * D_ * N_];
__device__ float g_V[B_ * D_ * N_];
__device__ float g_X[B_ * D_ * N_];

// ---------------------------------------------------------------------------
// Projection GEMM: C[b] = W @ X[b] + bias
//   W  [D, D] row-major (e, d)
//   X  [B, D, N] (n contiguous)
//   C  [B, D, N]
// 128x128 block tile, K-tile 16, 256 threads, 8x8 per-thread microtile.
// ---------------------------------------------------------------------------
__global__ __launch_bounds__(256, 2)
void proj_gemm_kernel(const float* __restrict__ W, const float* __restrict__ bias,
                      const float* __restrict__ X, float* __restrict__ C) {
    __shared__ float As[16][128];   // As[k][e]
    __shared__ float Bs[16][128];   // Bs[k][n]

    const int b  = blockIdx.z;
    const int n0 = blockIdx.x * 128;
    const int e0 = blockIdx.y * 128;
    const float* Xb = X + (size_t)b * DN_;
    float* Cb = C + (size_t)b * DN_;

    const int tid = threadIdx.x;
    const int tx = tid & 15;
    const int ty = tid >> 4;

    // load mappings
    const int we = tid >> 1;          // 0..127 (e row)
    const int wk = (tid & 1) * 8;     // 0 or 8  (k chunk)
    const int xk = tid >> 4;          // 0..15   (k row)
    const int xn = (tid & 15) * 8;    // 0..120  (n chunk)

    float acc[8][8];
#pragma unroll
    for (int i = 0; i < 8; i++)
#pragma unroll
        for (int j = 0; j < 8; j++) acc[i][j] = 0.f;

    for (int k0 = 0; k0 < D_; k0 += 16) {
        float4 w0 = *(const float4*)(W + (size_t)(e0 + we) * D_ + k0 + wk);
        float4 w1 = *(const float4*)(W + (size_t)(e0 + we) * D_ + k0 + wk + 4);
        float4 x0 = *(const float4*)(Xb + (size_t)(k0 + xk) * N_ + n0 + xn);
        float4 x1 = *(const float4*)(Xb + (size_t)(k0 + xk) * N_ + n0 + xn + 4);

        __syncthreads();   // previous iteration's compute done
        As[wk + 0][we] = w0.x; As[wk + 1][we] = w0.y;
        As[wk + 2][we] = w0.z; As[wk + 3][we] = w0.w;
        As[wk + 4][we] = w1.x; As[wk + 5][we] = w1.y;
        As[wk + 6][we] = w1.z; As[wk + 7][we] = w1.w;
        *(float4*)&Bs[xk][xn]     = x0;
        *(float4*)&Bs[xk][xn + 4] = x1;
        __syncthreads();

#pragma unroll
        for (int kk = 0; kk < 16; kk++) {
            float a[8], bb[8];
            *(float4*)(a)      = *(const float4*)&As[kk][ty * 8];
            *(float4*)(a + 4)  = *(const float4*)&As[kk][ty * 8 + 4];
            *(float4*)(bb)     = *(const float4*)&Bs[kk][tx * 8];
            *(float4*)(bb + 4) = *(const float4*)&Bs[kk][tx * 8 + 4];
#pragma unroll
            for (int i = 0; i < 8; i++)
#pragma unroll
                for (int j = 0; j < 8; j++)
                    acc[i][j] = fmaf(a[i], bb[j], acc[i][j]);
        }
    }

#pragma unroll
    for (int i = 0; i < 8; i++) {
        const int e = e0 + ty * 8 + i;
        const float be = __ldg(bias + e);
        float* cp = Cb + (size_t)e * N_ + n0 + tx * 8;
        float4 o0 = make_float4(acc[i][0] + be, acc[i][1] + be,
                                acc[i][2] + be, acc[i][3] + be);
        float4 o1 = make_float4(acc[i][4] + be, acc[i][5] + be,
                                acc[i][6] + be, acc[i][7] + be);
        *(float4*)cp       = o0;
        *(float4*)(cp + 4) = o1;
    }
}

// ---------------------------------------------------------------------------
// Flash attention, fp32. One CTA per (b, h, 64-query tile).
// Head layout: channel d = hd*H + h  (stride H in the D dimension).
// Per m-tile: S = (Q/8)^T K  (64x64x64), online softmax, O += P V^T.
// ---------------------------------------------------------------------------
#define VS_STRIDE 65
#define PS_STRIDE 68
#define ATTN_SMEM ((64 * 64 + 64 * 64 + 64 * VS_STRIDE + 64 * PS_STRIDE) * 4)

__global__ __launch_bounds__(256, 3)
void attn_kernel(const float* __restrict__ Q, const float* __restrict__ K,
                 const float* __restrict__ V, float* __restrict__ Xo) {
    extern __shared__ float sm[];
    float* qs = sm;                   // [64][64]   qs[hd][n]  (pre-scaled by 1/8)
    float* ks = sm + 64 * 64;         // [64][64]   ks[hd][m]
    float* vs = sm + 2 * 64 * 64;     // [64][65]   vs[hd][m]
    float* ps = vs + 64 * VS_STRIDE;  // [64][68]   ps[n][m]  (also output staging)

    const int n0 = blockIdx.x * 64;
    const int h  = blockIdx.y;
    const int b  = blockIdx.z;
    const int tid = threadIdx.x;
    const int tx = tid & 15;          // -> head-dim / m tile coord
    const int ty = tid >> 4;          // -> query-row tile coord

    const size_t base = ((size_t)b * D_ + h) * N_;   // add hd*H_*N_ per hd row

    // Load Q tile, fold in softmax scale 1/sqrt(64) = 0.125
#pragma unroll
    for (int it = 0; it < 4; it++) {
        int idx = tid + it * 256;     // float4 index among 1024
        int hd = idx >> 4;
        int nn = (idx & 15) * 4;
        float4 qv = *(const float4*)(Q + base + (size_t)hd * (H_ * N_) + n0 + nn);
        qv.x *= 0.125f; qv.y *= 0.125f; qv.z *= 0.125f; qv.w *= 0.125f;
        *(float4*)&qs[hd * 64 + nn] = qv;
    }

    float o[4][4];
    float mrow[4], lrow[4];
#pragma unroll
    for (int i = 0; i < 4; i++) {
        mrow[i] = -1e30f;
        lrow[i] = 0.f;
#pragma unroll
        for (int j = 0; j < 4; j++) o[i][j] = 0.f;
    }

    for (int m0 = 0; m0 < N_; m0 += 64) {
        __syncthreads();   // previous iteration done reading ks/vs/ps (also covers qs fill)

        // Load K, V tiles
#pragma unroll
        for (int it = 0; it < 4; it++) {
            int idx = tid + it * 256;
            int hd = idx >> 4;
            int mm = (idx & 15) * 4;
            const size_t g = base + (size_t)hd * (H_ * N_) + m0 + mm;
            *(float4*)&ks[hd * 64 + mm] = *(const float4*)(K + g);
            float4 vv = *(const float4*)(V + g);
            float* vp = &vs[hd * VS_STRIDE + mm];
            vp[0] = vv.x; vp[1] = vv.y; vp[2] = vv.z; vp[3] = vv.w;
        }
        __syncthreads();

        // S = q^T k : s[n=ty*4+i][m=tx*4+j]
        float s[4][4];
#pragma unroll
        for (int i = 0; i < 4; i++)
#pragma unroll
            for (int j = 0; j < 4; j++) s[i][j] = 0.f;

#pragma unroll 16
        for (int kk = 0; kk < 64; kk++) {
            float4 a  = *(const float4*)&qs[kk * 64 + ty * 4];
            float4 bb = *(const float4*)&ks[kk * 64 + tx * 4];
            float ar[4] = {a.x, a.y, a.z, a.w};
            float br[4] = {bb.x, bb.y, bb.z, bb.w};
#pragma unroll
            for (int i = 0; i < 4; i++)
#pragma unroll
                for (int j = 0; j < 4; j++)
                    s[i][j] = fmaf(ar[i], br[j], s[i][j]);
        }

        // Online softmax. Threads with the same ty occupy a contiguous 16-lane
        // group inside the warp, so xor-shuffles 8/4/2/1 reduce over the full
        // 64-column row.
#pragma unroll
        for (int i = 0; i < 4; i++) {
            float mx = fmaxf(fmaxf(s[i][0], s[i][1]), fmaxf(s[i][2], s[i][3]));
            mx = fmaxf(mx, __shfl_xor_sync(0xffffffffu, mx, 8));
            mx = fmaxf(mx, __shfl_xor_sync(0xffffffffu, mx, 4));
            mx = fmaxf(mx, __shfl_xor_sync(0xffffffffu, mx, 2));
            mx = fmaxf(mx, __shfl_xor_sync(0xffffffffu, mx, 1));
            float mnew = fmaxf(mrow[i], mx);
            float corr = __expf(mrow[i] - mnew);
            float rs = 0.f;
#pragma unroll
            for (int j = 0; j < 4; j++) {
                float p = __expf(s[i][j] - mnew);
                s[i][j] = p;
                rs += p;
            }
            rs += __shfl_xor_sync(0xffffffffu, rs, 8);
            rs += __shfl_xor_sync(0xffffffffu, rs, 4);
            rs += __shfl_xor_sync(0xffffffffu, rs, 2);
            rs += __shfl_xor_sync(0xffffffffu, rs, 1);
            lrow[i] = lrow[i] * corr + rs;
            mrow[i] = mnew;
#pragma unroll
            for (int j = 0; j < 4; j++) o[i][j] *= corr;
        }

        // Publish P tile: ps[n][m], float4 along m
#pragma unroll
        for (int i = 0; i < 4; i++)
            *(float4*)&ps[(ty * 4 + i) * PS_STRIDE + tx * 4] =
                make_float4(s[i][0], s[i][1], s[i][2], s[i][3]);
        __syncthreads();

        // O += P @ V^T : o[n=ty*4+i][hd=tx*4+j]
#pragma unroll 8
        for (int mm = 0; mm < 64; mm++) {
            float pv[4], vv[4];
#pragma unroll
            for (int i = 0; i < 4; i++) pv[i] = ps[(ty * 4 + i) * PS_STRIDE + mm];
#pragma unroll
            for (int j = 0; j < 4; j++) vv[j] = vs[(tx * 4 + j) * VS_STRIDE + mm];
#pragma unroll
            for (int i = 0; i < 4; i++)
#pragma unroll
                for (int j = 0; j < 4; j++)
                    o[i][j] = fmaf(pv[i], vv[j], o[i][j]);
        }
    }

    __syncthreads();
    // Normalize and stage into ps as [hd][n] for coalesced global write
    float rl[4];
#pragma unroll
    for (int i = 0; i < 4; i++) rl[i] = 1.f / lrow[i];
#pragma unroll
    for (int i = 0; i < 4; i++)
#pragma unroll
        for (int j = 0; j < 4; j++)
            ps[(tx * 4 + j) * PS_STRIDE + ty * 4 + i] = o[i][j] * rl[i];
    __syncthreads();

#pragma unroll
    for (int it = 0; it < 4; it++) {
        int idx = tid + it * 256;
        int hd = idx >> 4;
        int nn = (idx & 15) * 4;
        float4 val = *(const float4*)&ps[hd * PS_STRIDE + nn];
        *(float4*)(Xo + base + (size_t)hd * (H_ * N_) + n0 + nn) = val;
    }
}

// ---------------------------------------------------------------------------
extern "C" void kernel_launch(void* const* d_in, const int* in_sizes, int n_in,
                              void* d_out, int out_size) {
    const float* query  = (const float*)d_in[0];
    const float* key_in = (const float*)d_in[1];
    const float* value  = (const float*)d_in[2];
    const float* Wq = (const float*)d_in[3];
    const float* bq = (const float*)d_in[4];
    const float* Wk = (const float*)d_in[5];
    const float* bk = (const float*)d_in[6];
    const float* Wv = (const float*)d_in[7];
    const float* bv = (const float*)d_in[8];
    const float* Wm = (const float*)d_in[9];
    const float* bm = (const float*)d_in[10];
    float* out = (float*)d_out;

    float *Qp, *Kp, *Vp, *Xp;
    cudaGetSymbolAddress((void**)&Qp, g_Q);
    cudaGetSymbolAddress((void**)&Kp, g_K);
    cudaGetSymbolAddress((void**)&Vp, g_V);
    cudaGetSymbolAddress((void**)&Xp, g_X);

    cudaFuncSetAttribute(attn_kernel,
                         cudaFuncAttributeMaxDynamicSharedMemorySize, ATTN_SMEM);

    dim3 gp(N_ / 128, D_ / 128, B_);  // 16 x 8 x 4
    proj_gemm_kernel<<<gp, 256>>>(Wq, bq, query,  Qp);
    proj_gemm_kernel<<<gp, 256>>>(Wk, bk, key_in, Kp);
    proj_gemm_kernel<<<gp, 256>>>(Wv, bv, value,  Vp);

    dim3 ga(N_ / 64, H_, B_);         // 32 x 16 x 4
    attn_kernel<<<ga, 256, ATTN_SMEM>>>(Qp, Kp, Vp, Xp);

    proj_gemm_kernel<<<gp, 256>>>(Wm, bm, Xp, out);
}

// round 3
// speedup vs baseline: 2.9997x; 2.9997x over previous
#include <cuda_runtime.h>
#include <cstdint>

#define B_ 4
#define D_ 1024
#define N_ 2048
#define H_ 16
#define HD_ 64
#define HN_ (H_ * N_)
#define DN_ ((size_t)D_ * N_)

// Scratch (no runtime allocation allowed)
__device__ float g_Q[B_ * D_ * N_];
__device__ float g_K[B_ * D_ * N_];
__device__ float g_V[B_ * D_ * N_];
__device__ float g_X[B_ * D_ * N_];

// ---------------------------------------------------------------------------
// tf32 helpers
// ---------------------------------------------------------------------------
__device__ __forceinline__ uint32_t f2tf32(float f) {
    uint32_t u;
    asm("cvt.rna.tf32.f32 %0, %1;" : "=r"(u) : "f"(f));
    return u;
}

// D = A(16x8, row) * B(8x8, col) + D, tf32 in, fp32 acc
__device__ __forceinline__ void mma_tf32(float c[4], const uint32_t a[4],
                                         uint32_t b0, uint32_t b1) {
    asm volatile(
        "mma.sync.aligned.m16n8k8.row.col.f32.tf32.tf32.f32 "
        "{%0,%1,%2,%3}, {%4,%5,%6,%7}, {%8,%9}, {%0,%1,%2,%3};"
        : "+f"(c[0]), "+f"(c[1]), "+f"(c[2]), "+f"(c[3])
        : "r"(a[0]), "r"(a[1]), "r"(a[2]), "r"(a[3]), "r"(b0), "r"(b1));
}

// ---------------------------------------------------------------------------
// Projection GEMM (tf32 tensor): C[b] = W @ X[b] + bias
// CTA tile 128(e) x 128(n), K-tile 32. 8 warps in 2(M) x 4(N); warp = 64x32.
// ---------------------------------------------------------------------------
#define AS_STRIDE 36    // row length 32, pad to 36 (==4 mod 32) -> conflict-free A frags
#define BS_STRIDE 136   // row length 128, pad to 136 (==8 mod 32) -> conflict-free B frags

__global__ __launch_bounds__(256, 2)
void proj_gemm_kernel(const float* __restrict__ W, const float* __restrict__ bias,
                      const float* __restrict__ X, float* __restrict__ C) {
    __shared__ float As[128][AS_STRIDE];   // As[e][k]  (tf32 bits)
    __shared__ float Bs[32][BS_STRIDE];    // Bs[k][n]  (tf32 bits)

    const int b  = blockIdx.z;
    const int n0 = blockIdx.x * 128;
    const int e0 = blockIdx.y * 128;
    const float* Xb = X + (size_t)b * DN_;
    float* Cb = C + (size_t)b * DN_;

    const int tid  = threadIdx.x;
    const int wid  = tid >> 5;
    const int lane = tid & 31;
    const int g    = lane >> 2;
    const int tig  = lane & 3;
    const int wm   = wid >> 2;     // 0..1
    const int wn   = wid & 3;      // 0..3

    // global load mappings
    const int arow = tid >> 1;            // 0..127 (e)
    const int acol = (tid & 1) * 16;      // 0 or 16 (k)
    const int brow = tid >> 3;            // 0..31  (k)
    const int bc4  = tid & 7;             // float4 col base

    float acc[4][4][4];
#pragma unroll
    for (int mb = 0; mb < 4; mb++)
#pragma unroll
        for (int nb = 0; nb < 4; nb++)
#pragma unroll
            for (int c = 0; c < 4; c++) acc[mb][nb][c] = 0.f;

    for (int k0 = 0; k0 < D_; k0 += 32) {
        // global loads
        float4 wv[4], xv[4];
#pragma unroll
        for (int i = 0; i < 4; i++)
            wv[i] = *(const float4*)(W + (size_t)(e0 + arow) * D_ + k0 + acol + i * 4);
#pragma unroll
        for (int j = 0; j < 4; j++)
            xv[j] = *(const float4*)(Xb + (size_t)(k0 + brow) * N_ + n0 + (bc4 + j * 8) * 4);

        __syncthreads();
#pragma unroll
        for (int i = 0; i < 4; i++) {
            const int kk = acol + i * 4;
            As[arow][kk + 0] = __uint_as_float(f2tf32(wv[i].x));
            As[arow][kk + 1] = __uint_as_float(f2tf32(wv[i].y));
            As[arow][kk + 2] = __uint_as_float(f2tf32(wv[i].z));
            As[arow][kk + 3] = __uint_as_float(f2tf32(wv[i].w));
        }
#pragma unroll
        for (int j = 0; j < 4; j++) {
            const int nn = (bc4 + j * 8) * 4;
            Bs[brow][nn + 0] = __uint_as_float(f2tf32(xv[j].x));
            Bs[brow][nn + 1] = __uint_as_float(f2tf32(xv[j].y));
            Bs[brow][nn + 2] = __uint_as_float(f2tf32(xv[j].z));
            Bs[brow][nn + 3] = __uint_as_float(f2tf32(xv[j].w));
        }
        __syncthreads();

#pragma unroll
        for (int ks = 0; ks < 4; ks++) {
            const int kk = ks * 8;
            uint32_t a[4][4];
#pragma unroll
            for (int mb = 0; mb < 4; mb++) {
                const int r = wm * 64 + mb * 16;
                a[mb][0] = __float_as_uint(As[r + g][kk + tig]);
                a[mb][1] = __float_as_uint(As[r + g + 8][kk + tig]);
                a[mb][2] = __float_as_uint(As[r + g][kk + tig + 4]);
                a[mb][3] = __float_as_uint(As[r + g + 8][kk + tig + 4]);
            }
#pragma unroll
            for (int nb = 0; nb < 4; nb++) {
                const int cc = wn * 32 + nb * 8 + g;
                const uint32_t b0 = __float_as_uint(Bs[kk + tig][cc]);
                const uint32_t b1 = __float_as_uint(Bs[kk + tig + 4][cc]);
#pragma unroll
                for (int mb = 0; mb < 4; mb++)
                    mma_tf32(acc[mb][nb], a[mb], b0, b1);
            }
        }
    }

    // epilogue: bias + store (float2 per fragment half)
#pragma unroll
    for (int mb = 0; mb < 4; mb++) {
        const int e  = e0 + wm * 64 + mb * 16 + g;
        const float be0 = __ldg(bias + e);
        const float be1 = __ldg(bias + e + 8);
#pragma unroll
        for (int nb = 0; nb < 4; nb++) {
            const int col = n0 + wn * 32 + nb * 8 + 2 * tig;
            float2 v0 = make_float2(acc[mb][nb][0] + be0, acc[mb][nb][1] + be0);
            float2 v1 = make_float2(acc[mb][nb][2] + be1, acc[mb][nb][3] + be1);
            *(float2*)(Cb + (size_t)e * N_ + col)       = v0;
            *(float2*)(Cb + (size_t)(e + 8) * N_ + col) = v1;
        }
    }
}

// ---------------------------------------------------------------------------
// Flash attention, tf32 tensor path.
// CTA = (b, h, 128-query tile). 8 warps; warp wq owns queries [wq*16, wq*16+16).
// Key loop in 64-key tiles: S = Q^T K (tensor), online softmax (fp32),
// O += P V^T (tensor). P round-trips through warp-private SMEM.
// ---------------------------------------------------------------------------
#define QS_STRIDE 136  // row length 128, ==8 mod 32
#define KS_STRIDE 72   // row length 64,  ==8 mod 32
#define AVS_STRIDE 68  // row length 64,  ==4 mod 32
#define APS_STRIDE 68  // row length 64,  ==4 mod 32
#define PO_STRIDE 136

#define QS_OFF 0
#define KS_OFF (64 * QS_STRIDE)
#define VS_OFF (KS_OFF + 64 * KS_STRIDE)
#define PS_OFF (VS_OFF + 64 * AVS_STRIDE)
#define ATTN_SMEM ((PS_OFF + 128 * APS_STRIDE) * 4)   // 105472 bytes

__global__ __launch_bounds__(256, 2)
void attn_kernel(const float* __restrict__ Q, const float* __restrict__ K,
                 const float* __restrict__ V, float* __restrict__ Xo) {
    extern __shared__ float sm[];
    float* qs = sm + QS_OFF;   // [64 hd][128 q]  tf32 (pre-scaled by 1/8)
    float* ks = sm + KS_OFF;   // [64 hd][64 key] tf32
    float* vs = sm + VS_OFF;   // [64 hd][64 key] tf32
    float* ps = sm + PS_OFF;   // [128 q][64 key] tf32 P; reused as [64 hd][128 q] out

    const int n0  = blockIdx.x * 128;
    const int h   = blockIdx.y;
    const int b   = blockIdx.z;
    const int tid = threadIdx.x;
    const int wid  = tid >> 5;
    const int lane = tid & 31;
    const int g    = lane >> 2;
    const int tig  = lane & 3;
    const int qrow = wid * 16;   // this warp's query block

    const size_t base = ((size_t)b * D_ + h) * N_;

    // Load Q tile (scaled, tf32)
#pragma unroll
    for (int it = 0; it < 8; it++) {
        const int idx = tid + it * 256;
        const int hd  = idx >> 5;
        const int q4  = (idx & 31) * 4;
        float4 qv = *(const float4*)(Q + base + (size_t)hd * HN_ + n0 + q4);
        float* qp = &qs[hd * QS_STRIDE + q4];
        qp[0] = __uint_as_float(f2tf32(qv.x * 0.125f));
        qp[1] = __uint_as_float(f2tf32(qv.y * 0.125f));
        qp[2] = __uint_as_float(f2tf32(qv.z * 0.125f));
        qp[3] = __uint_as_float(f2tf32(qv.w * 0.125f));
    }

    float o[8][4];
    float mrow[2], lrow[2];
#pragma unroll
    for (int nb = 0; nb < 8; nb++)
#pragma unroll
        for (int c = 0; c < 4; c++) o[nb][c] = 0.f;
    mrow[0] = mrow[1] = -1e30f;
    lrow[0] = lrow[1] = 0.f;

    for (int m0 = 0; m0 < N_; m0 += 64) {
        __syncthreads();   // prior tile's consumers done with ks/vs (covers qs fill on iter 0)
        // Load K, V tiles (tf32)
#pragma unroll
        for (int it = 0; it < 4; it++) {
            const int idx = tid + it * 256;
            const int hd  = idx >> 4;
            const int m4  = (idx & 15) * 4;
            const size_t gaddr = base + (size_t)hd * HN_ + m0 + m4;
            float4 kv = *(const float4*)(K + gaddr);
            float4 vv = *(const float4*)(V + gaddr);
            float* kp = &ks[hd * KS_STRIDE + m4];
            kp[0] = __uint_as_float(f2tf32(kv.x));
            kp[1] = __uint_as_float(f2tf32(kv.y));
            kp[2] = __uint_as_float(f2tf32(kv.z));
            kp[3] = __uint_as_float(f2tf32(kv.w));
            float* vp = &vs[hd * AVS_STRIDE + m4];
            vp[0] = __uint_as_float(f2tf32(vv.x));
            vp[1] = __uint_as_float(f2tf32(vv.y));
            vp[2] = __uint_as_float(f2tf32(vv.z));
            vp[3] = __uint_as_float(f2tf32(vv.w));
        }
        __syncthreads();

        // S = Q^T K : warp computes 16q x 64key
        float s[8][4];
#pragma unroll
        for (int nb = 0; nb < 8; nb++)
#pragma unroll
            for (int c = 0; c < 4; c++) s[nb][c] = 0.f;

#pragma unroll
        for (int ksp = 0; ksp < 8; ksp++) {
            const int kk = ksp * 8;
            uint32_t a[4];
            a[0] = __float_as_uint(qs[(kk + tig) * QS_STRIDE + qrow + g]);
            a[1] = __float_as_uint(qs[(kk + tig) * QS_STRIDE + qrow + g + 8]);
            a[2] = __float_as_uint(qs[(kk + tig + 4) * QS_STRIDE + qrow + g]);
            a[3] = __float_as_uint(qs[(kk + tig + 4) * QS_STRIDE + qrow + g + 8]);
#pragma unroll
            for (int nb = 0; nb < 8; nb++) {
                const int key = nb * 8 + g;
                const uint32_t b0 = __float_as_uint(ks[(kk + tig) * KS_STRIDE + key]);
                const uint32_t b1 = __float_as_uint(ks[(kk + tig + 4) * KS_STRIDE + key]);
                mma_tf32(s[nb], a, b0, b1);
            }
        }

        // Online softmax per row (rows g and g+8; each row lives in one lane-quad)
#pragma unroll
        for (int r = 0; r < 2; r++) {
            float mx = -1e30f;
#pragma unroll
            for (int nb = 0; nb < 8; nb++)
                mx = fmaxf(mx, fmaxf(s[nb][2 * r], s[nb][2 * r + 1]));
            mx = fmaxf(mx, __shfl_xor_sync(0xffffffffu, mx, 1));
            mx = fmaxf(mx, __shfl_xor_sync(0xffffffffu, mx, 2));
            const float mnew = fmaxf(mrow[r], mx);
            const float corr = __expf(mrow[r] - mnew);
            mrow[r] = mnew;
            float rs = 0.f;
#pragma unroll
            for (int nb = 0; nb < 8; nb++) {
                float p0 = __expf(s[nb][2 * r] - mnew);
                float p1 = __expf(s[nb][2 * r + 1] - mnew);
                s[nb][2 * r] = p0;
                s[nb][2 * r + 1] = p1;
                rs += p0 + p1;
            }
            rs += __shfl_xor_sync(0xffffffffu, rs, 1);
            rs += __shfl_xor_sync(0xffffffffu, rs, 2);
            lrow[r] = lrow[r] * corr + rs;
#pragma unroll
            for (int nb = 0; nb < 8; nb++) {
                o[nb][2 * r]     *= corr;
                o[nb][2 * r + 1] *= corr;
            }
        }

        // Publish P (warp-private rows) as tf32
#pragma unroll
        for (int nb = 0; nb < 8; nb++) {
            const int col = nb * 8 + 2 * tig;
            float2 p0 = make_float2(__uint_as_float(f2tf32(s[nb][0])),
                                    __uint_as_float(f2tf32(s[nb][1])));
            float2 p1 = make_float2(__uint_as_float(f2tf32(s[nb][2])),
                                    __uint_as_float(f2tf32(s[nb][3])));
            *(float2*)&ps[(qrow + g) * APS_STRIDE + col]     = p0;
            *(float2*)&ps[(qrow + g + 8) * APS_STRIDE + col] = p1;
        }
        __syncwarp();

        // O += P V^T : 16q x 64hd, K = 64 keys
#pragma unroll
        for (int ksp = 0; ksp < 8; ksp++) {
            const int kk = ksp * 8;
            uint32_t pa[4];
            pa[0] = __float_as_uint(ps[(qrow + g) * APS_STRIDE + kk + tig]);
            pa[1] = __float_as_uint(ps[(qrow + g + 8) * APS_STRIDE + kk + tig]);
            pa[2] = __float_as_uint(ps[(qrow + g) * APS_STRIDE + kk + tig + 4]);
            pa[3] = __float_as_uint(ps[(qrow + g + 8) * APS_STRIDE + kk + tig + 4]);
#pragma unroll
            for (int nb = 0; nb < 8; nb++) {
                const int hd = nb * 8 + g;
                const uint32_t b0 = __float_as_uint(vs[hd * AVS_STRIDE + kk + tig]);
                const uint32_t b1 = __float_as_uint(vs[hd * AVS_STRIDE + kk + tig + 4]);
                mma_tf32(o[nb], pa, b0, b1);
            }
        }
        __syncwarp();   // P region stable until next tile's writes (warp-private)
    }

    __syncthreads();   // everyone done with ps as P before reuse as output staging

    // Normalize and stage as [hd][q] for coalesced store
    const float rl0 = 1.f / lrow[0];
    const float rl1 = 1.f / lrow[1];
#pragma unroll
    for (int nb = 0; nb < 8; nb++) {
        const int hd0 = nb * 8 + 2 * tig;
        ps[hd0 * PO_STRIDE + qrow + g]           = o[nb][0] * rl0;
        ps[(hd0 + 1) * PO_STRIDE + qrow + g]     = o[nb][1] * rl0;
        ps[hd0 * PO_STRIDE + qrow + g + 8]       = o[nb][2] * rl1;
        ps[(hd0 + 1) * PO_STRIDE + qrow + g + 8] = o[nb][3] * rl1;
    }
    __syncthreads();

#pragma unroll
    for (int it = 0; it < 8; it++) {
        const int idx = tid + it * 256;
        const int hd  = idx >> 5;
        const int q4  = (idx & 31) * 4;
        float4 val = *(const float4*)&ps[hd * PO_STRIDE + q4];
        *(float4*)(Xo + base + (size_t)hd * HN_ + n0 + q4) = val;
    }
}

// ---------------------------------------------------------------------------
extern "C" void kernel_launch(void* const* d_in, const int* in_sizes, int n_in,
                              void* d_out, int out_size) {
    const float* query  = (const float*)d_in[0];
    const float* key_in = (const float*)d_in[1];
    const float* value  = (const float*)d_in[2];
    const float* Wq = (const float*)d_in[3];
    const float* bq = (const float*)d_in[4];
    const float* Wk = (const float*)d_in[5];
    const float* bk = (const float*)d_in[6];
    const float* Wv = (const float*)d_in[7];
    const float* bv = (const float*)d_in[8];
    const float* Wm = (const float*)d_in[9];
    const float* bm = (const float*)d_in[10];
    float* out = (float*)d_out;

    float *Qp, *Kp, *Vp, *Xp;
    cudaGetSymbolAddress((void**)&Qp, g_Q);
    cudaGetSymbolAddress((void**)&Kp, g_K);
    cudaGetSymbolAddress((void**)&Vp, g_V);
    cudaGetSymbolAddress((void**)&Xp, g_X);

    cudaFuncSetAttribute(attn_kernel,
                         cudaFuncAttributeMaxDynamicSharedMemorySize, ATTN_SMEM);

    dim3 gp(N_ / 128, D_ / 128, B_);   // 16 x 8 x 4
    proj_gemm_kernel<<<gp, 256>>>(Wq, bq, query,  Qp);
    proj_gemm_kernel<<<gp, 256>>>(Wk, bk, key_in, Kp);
    proj_gemm_kernel<<<gp, 256>>>(Wv, bv, value,  Vp);

    dim3 ga(N_ / 128, H_, B_);         // 16 x 16 x 4
    attn_kernel<<<ga, 256, ATTN_SMEM>>>(Qp, Kp, Vp, Xp);

    proj_gemm_kernel<<<gp, 256>>>(Wm, bm, Xp, out);
}